// round 14
// baseline (speedup 1.0000x reference)
#include <cuda_runtime.h>
#include <cuda_fp16.h>
#include <cstdint>
#include <cstddef>

// ---------------------------------------------------------------------------
// GCN_21569325760838: 2-layer GCN. CSR-gather (masked x8), fp16 mma GEMMs
// (fp32 accum, full-K smem resident, 3 CTAs/SM), fp16 intermediates,
// single-pass decoupled-lookback scan, fork-join overlap.
//   h1  = x @ W1                        (UNSCALED fp16)
//   a1  = relu(dinv[d]*(sum_s dinv[s]*h1[s] + dinv[d]*h1[d]) + b1)
//   hs2 = dinv[row] * (a1 @ W2)
//   out = dinv[d]*(sum hs2[s] + hs2[d]) + b2
// ---------------------------------------------------------------------------

#define NMAX 100000
#define EMAX 1600000
#define NF1  128
#define NF2  64
#define SCAN_ELEMS 1024

__device__ int    g_is64 = 1;
__device__ int    g_deg [NMAX];
__device__ int    g_off [NMAX + 1];
__device__ int    g_cur [NMAX];
__device__ int    g_csr [EMAX];
__device__ int    g_src32[EMAX];
__device__ int    g_dst32[EMAX];
__device__ volatile int g_bsum [128];   // inclusive prefix through block b
__device__ volatile int g_bflag[128];   // block-b prefix published
__device__ float  g_dinv[NMAX];
__device__ __half g_h1  [(size_t)NMAX * NF1];   // UNSCALED x@W1
__device__ __half g_a1  [(size_t)NMAX * NF1];
__device__ __half g_h2  [(size_t)NMAX * NF2];   // dinv-scaled a1@W2
__device__ __half g_w1t [NF1 * NF1];
__device__ __half g_w2t [NF2 * NF1];

// ---------------------------------------------------------------------------
__global__ void k_init(const long long* __restrict__ p, int nscan, int n,
                       const float* __restrict__ W1, const float* __restrict__ W2) {
    int i = blockIdx.x * blockDim.x + threadIdx.x;
    if (i < n) g_deg[i] = 0;
    if (i < 128) g_bflag[i] = 0;          // reset lookback flags each replay
    if (i < nscan) {
        long long v = p[i];
        if (v < 0 || v >= (long long)n) g_is64 = 0;
    }
    if (i < NF1 * NF1) {
        int nn = i / NF1, k = i % NF1;
        g_w1t[i] = __float2half(W1[(size_t)k * NF1 + nn]);
    }
    if (i < NF2 * NF1) {
        int nn = i / NF1, k = i % NF1;
        g_w2t[i] = __float2half(W2[(size_t)k * NF2 + nn]);
    }
}

__global__ void k_deg(const void* __restrict__ eidx, int E) {
    int i = blockIdx.x * blockDim.x + threadIdx.x;
    int e0 = i * 2;
    if (e0 >= E) return;
    int s0, s1 = -1, d0, d1 = -1;
    if (g_is64) {
        const long long* p = (const long long*)eidx;
        if (e0 + 1 < E) {
            longlong2 sv = __ldg((const longlong2*)(p + e0));
            longlong2 dv = __ldg((const longlong2*)(p + E + e0));
            s0 = (int)sv.x; s1 = (int)sv.y;
            d0 = (int)dv.x; d1 = (int)dv.y;
        } else {
            s0 = (int)__ldg(p + e0);
            d0 = (int)__ldg(p + E + e0);
        }
    } else {
        const int* p = (const int*)eidx;
        if (e0 + 1 < E) {
            int2 sv = __ldg((const int2*)(p + e0));
            int2 dv = __ldg((const int2*)(p + E + e0));
            s0 = sv.x; s1 = sv.y;
            d0 = dv.x; d1 = dv.y;
        } else {
            s0 = __ldg(p + e0);
            d0 = __ldg(p + E + e0);
        }
    }
    g_src32[e0] = s0;
    g_dst32[e0] = d0;
    atomicAdd(&g_deg[d0], 1);
    if (s1 >= 0) {
        g_src32[e0 + 1] = s1;
        g_dst32[e0 + 1] = d1;
        atomicAdd(&g_deg[d1], 1);
    }
}

// ---------------------------------------------------------------------------
// Single-pass scan with decoupled lookback. Grid = ceil(n/1024) = 98 blocks,
// all resident on 148 SMs -> spin on predecessor is deadlock-free.
__global__ void k_scanL(int n, int E) {
    __shared__ int sm[256];
    __shared__ int s_prefix;
    const int b = blockIdx.x;
    const int t = threadIdx.x;
    const int i0 = b * SCAN_ELEMS + t * 4;
    int vals[4];
    int s = 0;
    #pragma unroll
    for (int k = 0; k < 4; k++) {
        int i = i0 + k;
        vals[k] = (i < n) ? g_deg[i] : 0;
        s += vals[k];
    }
    sm[t] = s;
    __syncthreads();
    #pragma unroll
    for (int st = 1; st < 256; st <<= 1) {
        int u = (t >= st) ? sm[t - st] : 0;
        __syncthreads();
        sm[t] += u;
        __syncthreads();
    }
    if (t == 0) {
        int prefix = 0;
        if (b > 0) {
            while (g_bflag[b - 1] == 0) { }
            prefix = g_bsum[b - 1];
        }
        g_bsum[b] = prefix + sm[255];
        __threadfence();
        g_bflag[b] = 1;
        s_prefix = prefix;
    }
    __syncthreads();
    int base = s_prefix + sm[t] - s;     // global exclusive prefix
    #pragma unroll
    for (int k = 0; k < 4; k++) {
        int i = i0 + k;
        if (i < n) {
            g_off[i] = base;
            g_cur[i] = base;
            g_dinv[i] = rsqrtf((float)(vals[k] + 1));
            base += vals[k];
        }
    }
    if (b == 0 && t == 0) g_off[n] = E;
}

__global__ void k_scatter(int E) {
    int i = blockIdx.x * blockDim.x + threadIdx.x;
    int e0 = i * 2;
    if (e0 >= E) return;
    if (e0 + 1 < E) {
        int2 d = __ldg((const int2*)(g_dst32 + e0));
        int2 s = __ldg((const int2*)(g_src32 + e0));
        int p0 = atomicAdd(&g_cur[d.x], 1);
        g_csr[p0] = s.x;
        int p1 = atomicAdd(&g_cur[d.y], 1);
        g_csr[p1] = s.y;
    } else {
        int d = g_dst32[e0];
        int p0 = atomicAdd(&g_cur[d], 1);
        g_csr[p0] = g_src32[e0];
    }
}

// ---------------------------------------------------------------------------
// GEMM1: fp16 mma, FULL-K resident. C fp16 = A_f32[M,128] @ W1 (UNSCALED).
// Block 64x128, 8 warps, warp tile 32x32, dynamic smem, 3 CTAs/SM.
// ---------------------------------------------------------------------------
#define G1_BM 64
#define G1_BN 128
#define G1_ST (NF1 + 8)
#define G1_SMEM ((G1_BM + G1_BN) * G1_ST * 2)

__global__ void __launch_bounds__(256, 3)
gemm1_fp16(const float* __restrict__ A, __half* __restrict__ C, int M) {
    constexpr int BM = G1_BM, BN = G1_BN, K = NF1, ST = G1_ST;
    constexpr int WNUM = BN / 32;
    extern __shared__ __half smem[];
    __half* As = smem;
    __half* Bs = smem + BM * ST;

    const int tid  = threadIdx.x;
    const int lane = tid & 31;
    const int warp = tid >> 5;
    const int gid  = lane >> 2;
    const int tig  = lane & 3;
    const int wm   = (warp / WNUM) * 32;
    const int wn   = (warp % WNUM) * 32;
    const int row0 = blockIdx.x * BM;

    #pragma unroll
    for (int idx = tid; idx < BM * (K / 4); idx += 256) {
        int r = idx / (K / 4), c4 = (idx % (K / 4)) * 4;
        float4 v = make_float4(0.f, 0.f, 0.f, 0.f);
        if (row0 + r < M)
            v = *(const float4*)(A + (size_t)(row0 + r) * K + c4);
        uint2 o;
        *(__half2*)&o.x = __floats2half2_rn(v.x, v.y);
        *(__half2*)&o.y = __floats2half2_rn(v.z, v.w);
        *(uint2*)&As[r * ST + c4] = o;
    }
    #pragma unroll
    for (int idx = tid; idx < BN * (K / 4); idx += 256) {
        int n = idx / (K / 4), c4 = (idx % (K / 4)) * 4;
        *(uint2*)&Bs[n * ST + c4] = *(const uint2*)(g_w1t + (size_t)n * K + c4);
    }
    __syncthreads();

    float acc[2][4][4];
    #pragma unroll
    for (int mt = 0; mt < 2; mt++)
        #pragma unroll
        for (int nt = 0; nt < 4; nt++)
            #pragma unroll
            for (int i = 0; i < 4; i++) acc[mt][nt][i] = 0.f;

    #pragma unroll
    for (int ks = 0; ks < K / 16; ks++) {
        const int kk = ks * 16;
        uint32_t af[2][4];
        #pragma unroll
        for (int mt = 0; mt < 2; mt++) {
            int rb = wm + mt * 16 + gid;
            af[mt][0] = *(const uint32_t*)&As[rb * ST + kk + 2 * tig];
            af[mt][1] = *(const uint32_t*)&As[(rb + 8) * ST + kk + 2 * tig];
            af[mt][2] = *(const uint32_t*)&As[rb * ST + kk + 2 * tig + 8];
            af[mt][3] = *(const uint32_t*)&As[(rb + 8) * ST + kk + 2 * tig + 8];
        }
        uint32_t bf[4][2];
        #pragma unroll
        for (int nt = 0; nt < 4; nt++) {
            int cb = wn + nt * 8 + gid;
            bf[nt][0] = *(const uint32_t*)&Bs[cb * ST + kk + 2 * tig];
            bf[nt][1] = *(const uint32_t*)&Bs[cb * ST + kk + 2 * tig + 8];
        }
        #pragma unroll
        for (int mt = 0; mt < 2; mt++)
            #pragma unroll
            for (int nt = 0; nt < 4; nt++) {
                asm volatile(
                    "mma.sync.aligned.m16n8k16.row.col.f32.f16.f16.f32 "
                    "{%0,%1,%2,%3}, {%4,%5,%6,%7}, {%8,%9}, {%0,%1,%2,%3};\n"
                    : "+f"(acc[mt][nt][0]), "+f"(acc[mt][nt][1]),
                      "+f"(acc[mt][nt][2]), "+f"(acc[mt][nt][3])
                    : "r"(af[mt][0]), "r"(af[mt][1]),
                      "r"(af[mt][2]), "r"(af[mt][3]),
                      "r"(bf[nt][0]), "r"(bf[nt][1]));
            }
    }

    #pragma unroll
    for (int mt = 0; mt < 2; mt++) {
        int r0 = row0 + wm + mt * 16 + gid;
        int r1 = r0 + 8;
        #pragma unroll
        for (int nt = 0; nt < 4; nt++) {
            int col = wn + nt * 8 + 2 * tig;
            if (r0 < M)
                *(__half2*)(C + (size_t)r0 * BN + col) =
                    __floats2half2_rn(acc[mt][nt][0], acc[mt][nt][1]);
            if (r1 < M)
                *(__half2*)(C + (size_t)r1 * BN + col) =
                    __floats2half2_rn(acc[mt][nt][2], acc[mt][nt][3]);
        }
    }
}

// ---------------------------------------------------------------------------
// GEMM2: fp16 mma, FULL-K resident. C fp16 = rowscale*(A_f16 @ W2).
// Block 128x64, 8 warps, warp tile 32x32, dynamic smem, 3 CTAs/SM.
// ---------------------------------------------------------------------------
#define G2_BM 128
#define G2_BN 64
#define G2_ST (NF1 + 8)
#define G2_SMEM ((G2_BM + G2_BN) * G2_ST * 2)

__global__ void __launch_bounds__(256, 3)
gemm2_fp16(const __half* __restrict__ A, __half* __restrict__ C,
           const float* __restrict__ rowscale, int M) {
    constexpr int BM = G2_BM, BN = G2_BN, K = NF1, ST = G2_ST;
    constexpr int WNUM = BN / 32;
    extern __shared__ __half smem[];
    __half* As = smem;
    __half* Bs = smem + BM * ST;

    const int tid  = threadIdx.x;
    const int lane = tid & 31;
    const int warp = tid >> 5;
    const int gid  = lane >> 2;
    const int tig  = lane & 3;
    const int wm   = (warp / WNUM) * 32;
    const int wn   = (warp % WNUM) * 32;
    const int row0 = blockIdx.x * BM;

    #pragma unroll
    for (int idx = tid; idx < BM * (K / 4); idx += 256) {
        int r = idx / (K / 4), c4 = (idx % (K / 4)) * 4;
        uint2 v = make_uint2(0u, 0u);
        if (row0 + r < M)
            v = *(const uint2*)(A + (size_t)(row0 + r) * K + c4);
        *(uint2*)&As[r * ST + c4] = v;
    }
    #pragma unroll
    for (int idx = tid; idx < BN * (K / 4); idx += 256) {
        int n = idx / (K / 4), c4 = (idx % (K / 4)) * 4;
        *(uint2*)&Bs[n * ST + c4] = *(const uint2*)(g_w2t + (size_t)n * K + c4);
    }
    __syncthreads();

    float acc[2][4][4];
    #pragma unroll
    for (int mt = 0; mt < 2; mt++)
        #pragma unroll
        for (int nt = 0; nt < 4; nt++)
            #pragma unroll
            for (int i = 0; i < 4; i++) acc[mt][nt][i] = 0.f;

    #pragma unroll
    for (int ks = 0; ks < K / 16; ks++) {
        const int kk = ks * 16;
        uint32_t af[2][4];
        #pragma unroll
        for (int mt = 0; mt < 2; mt++) {
            int rb = wm + mt * 16 + gid;
            af[mt][0] = *(const uint32_t*)&As[rb * ST + kk + 2 * tig];
            af[mt][1] = *(const uint32_t*)&As[(rb + 8) * ST + kk + 2 * tig];
            af[mt][2] = *(const uint32_t*)&As[rb * ST + kk + 2 * tig + 8];
            af[mt][3] = *(const uint32_t*)&As[(rb + 8) * ST + kk + 2 * tig + 8];
        }
        uint32_t bf[4][2];
        #pragma unroll
        for (int nt = 0; nt < 4; nt++) {
            int cb = wn + nt * 8 + gid;
            bf[nt][0] = *(const uint32_t*)&Bs[cb * ST + kk + 2 * tig];
            bf[nt][1] = *(const uint32_t*)&Bs[cb * ST + kk + 2 * tig + 8];
        }
        #pragma unroll
        for (int mt = 0; mt < 2; mt++)
            #pragma unroll
            for (int nt = 0; nt < 4; nt++) {
                asm volatile(
                    "mma.sync.aligned.m16n8k16.row.col.f32.f16.f16.f32 "
                    "{%0,%1,%2,%3}, {%4,%5,%6,%7}, {%8,%9}, {%0,%1,%2,%3};\n"
                    : "+f"(acc[mt][nt][0]), "+f"(acc[mt][nt][1]),
                      "+f"(acc[mt][nt][2]), "+f"(acc[mt][nt][3])
                    : "r"(af[mt][0]), "r"(af[mt][1]),
                      "r"(af[mt][2]), "r"(af[mt][3]),
                      "r"(bf[nt][0]), "r"(bf[nt][1]));
            }
    }

    #pragma unroll
    for (int mt = 0; mt < 2; mt++) {
        int r0 = row0 + wm + mt * 16 + gid;
        int r1 = r0 + 8;
        #pragma unroll
        for (int nt = 0; nt < 4; nt++) {
            int col = wn + nt * 8 + 2 * tig;
            if (r0 < M) {
                float sc = rowscale[r0];
                *(__half2*)(C + (size_t)r0 * BN + col) =
                    __floats2half2_rn(acc[mt][nt][0] * sc, acc[mt][nt][1] * sc);
            }
            if (r1 < M) {
                float sc = rowscale[r1];
                *(__half2*)(C + (size_t)r1 * BN + col) =
                    __floats2half2_rn(acc[mt][nt][2] * sc, acc[mt][nt][3] * sc);
            }
        }
    }
}

// ---------------------------------------------------------------------------
// Layer-1 aggregation over UNSCALED h1. Masked full-width x8 loop.
__global__ void k_agg1(const float* __restrict__ b1, int n) {
    int node = blockIdx.x * (blockDim.x >> 5) + (threadIdx.x >> 5);
    if (node >= n) return;
    int lane = threadIdx.x & 31;

    const uint2* h = (const uint2*)g_h1;
    const float w = __ldg(&g_dinv[node]);

    uint2 sv = __ldg(&h[(size_t)node * 32 + lane]);
    float2 lo = __half22float2(*(__half2*)&sv.x);
    float2 hi = __half22float2(*(__half2*)&sv.y);
    float4 acc = make_float4(w * lo.x, w * lo.y, w * hi.x, w * hi.y);

    int j = g_off[node];
    const int jend = g_off[node + 1];
    while (j < jend) {
        int cnt = min(32, jend - j);
        int sidx = 0; float dv = 0.f;
        if (lane < cnt) { sidx = __ldg(&g_csr[j + lane]); dv = __ldg(&g_dinv[sidx]); }
        for (int t = 0; t < cnt; t += 8) {
            int s0 = __shfl_sync(0xffffffffu, sidx, t);
            int s1 = __shfl_sync(0xffffffffu, sidx, t + 1);
            int s2 = __shfl_sync(0xffffffffu, sidx, t + 2);
            int s3 = __shfl_sync(0xffffffffu, sidx, t + 3);
            int s4 = __shfl_sync(0xffffffffu, sidx, t + 4);
            int s5 = __shfl_sync(0xffffffffu, sidx, t + 5);
            int s6 = __shfl_sync(0xffffffffu, sidx, t + 6);
            int s7 = __shfl_sync(0xffffffffu, sidx, t + 7);
            float f0 = __shfl_sync(0xffffffffu, dv, t);
            float f1 = __shfl_sync(0xffffffffu, dv, t + 1);
            float f2 = __shfl_sync(0xffffffffu, dv, t + 2);
            float f3 = __shfl_sync(0xffffffffu, dv, t + 3);
            float f4 = __shfl_sync(0xffffffffu, dv, t + 4);
            float f5 = __shfl_sync(0xffffffffu, dv, t + 5);
            float f6 = __shfl_sync(0xffffffffu, dv, t + 6);
            float f7 = __shfl_sync(0xffffffffu, dv, t + 7);
            uint2 v0 = __ldg(&h[(size_t)s0 * 32 + lane]);
            uint2 v1 = __ldg(&h[(size_t)s1 * 32 + lane]);
            uint2 v2 = __ldg(&h[(size_t)s2 * 32 + lane]);
            uint2 v3 = __ldg(&h[(size_t)s3 * 32 + lane]);
            uint2 v4 = __ldg(&h[(size_t)s4 * 32 + lane]);
            uint2 v5 = __ldg(&h[(size_t)s5 * 32 + lane]);
            uint2 v6 = __ldg(&h[(size_t)s6 * 32 + lane]);
            uint2 v7 = __ldg(&h[(size_t)s7 * 32 + lane]);
            float2 p0 = __half22float2(*(__half2*)&v0.x), q0 = __half22float2(*(__half2*)&v0.y);
            float2 p1 = __half22float2(*(__half2*)&v1.x), q1 = __half22float2(*(__half2*)&v1.y);
            float2 p2 = __half22float2(*(__half2*)&v2.x), q2 = __half22float2(*(__half2*)&v2.y);
            float2 p3 = __half22float2(*(__half2*)&v3.x), q3 = __half22float2(*(__half2*)&v3.y);
            float2 p4 = __half22float2(*(__half2*)&v4.x), q4 = __half22float2(*(__half2*)&v4.y);
            float2 p5 = __half22float2(*(__half2*)&v5.x), q5 = __half22float2(*(__half2*)&v5.y);
            float2 p6 = __half22float2(*(__half2*)&v6.x), q6 = __half22float2(*(__half2*)&v6.y);
            float2 p7 = __half22float2(*(__half2*)&v7.x), q7 = __half22float2(*(__half2*)&v7.y);
            acc.x = fmaf(f0, p0.x, fmaf(f1, p1.x, fmaf(f2, p2.x, fmaf(f3, p3.x, acc.x))));
            acc.x = fmaf(f4, p4.x, fmaf(f5, p5.x, fmaf(f6, p6.x, fmaf(f7, p7.x, acc.x))));
            acc.y = fmaf(f0, p0.y, fmaf(f1, p1.y, fmaf(f2, p2.y, fmaf(f3, p3.y, acc.y))));
            acc.y = fmaf(f4, p4.y, fmaf(f5, p5.y, fmaf(f6, p6.y, fmaf(f7, p7.y, acc.y))));
            acc.z = fmaf(f0, q0.x, fmaf(f1, q1.x, fmaf(f2, q2.x, fmaf(f3, q3.x, acc.z))));
            acc.z = fmaf(f4, q4.x, fmaf(f5, q5.x, fmaf(f6, q6.x, fmaf(f7, q7.x, acc.z))));
            acc.w = fmaf(f0, q0.y, fmaf(f1, q1.y, fmaf(f2, q2.y, fmaf(f3, q3.y, acc.w))));
            acc.w = fmaf(f4, q4.y, fmaf(f5, q5.y, fmaf(f6, q6.y, fmaf(f7, q7.y, acc.w))));
        }
        j += cnt;
    }
    float4 b = ((const float4*)b1)[lane];
    uint2 o;
    *(__half2*)&o.x = __floats2half2_rn(fmaxf(acc.x * w + b.x, 0.f),
                                        fmaxf(acc.y * w + b.y, 0.f));
    *(__half2*)&o.y = __floats2half2_rn(fmaxf(acc.z * w + b.z, 0.f),
                                        fmaxf(acc.w * w + b.w, 0.f));
    ((uint2*)g_a1)[(size_t)node * 32 + lane] = o;
}

// Layer-2 aggregation over pre-scaled h2. Masked full-width x8; fp32 out.
__global__ void k_agg2(const float* __restrict__ b2, float* __restrict__ out, int n) {
    int node = blockIdx.x * (blockDim.x >> 5) + (threadIdx.x >> 5);
    if (node >= n) return;
    int lane = threadIdx.x & 31;

    const __half2* h = (const __half2*)g_h2;
    float2 acc = __half22float2(__ldg(&h[(size_t)node * 32 + lane]));
    int j = g_off[node];
    const int jend = g_off[node + 1];
    while (j < jend) {
        int cnt = min(32, jend - j);
        int sidx = 0; float dv = 0.f;
        if (lane < cnt) { sidx = __ldg(&g_csr[j + lane]); dv = 1.0f; }
        for (int t = 0; t < cnt; t += 8) {
            int s0 = __shfl_sync(0xffffffffu, sidx, t);
            int s1 = __shfl_sync(0xffffffffu, sidx, t + 1);
            int s2 = __shfl_sync(0xffffffffu, sidx, t + 2);
            int s3 = __shfl_sync(0xffffffffu, sidx, t + 3);
            int s4 = __shfl_sync(0xffffffffu, sidx, t + 4);
            int s5 = __shfl_sync(0xffffffffu, sidx, t + 5);
            int s6 = __shfl_sync(0xffffffffu, sidx, t + 6);
            int s7 = __shfl_sync(0xffffffffu, sidx, t + 7);
            float f0 = __shfl_sync(0xffffffffu, dv, t);
            float f1 = __shfl_sync(0xffffffffu, dv, t + 1);
            float f2 = __shfl_sync(0xffffffffu, dv, t + 2);
            float f3 = __shfl_sync(0xffffffffu, dv, t + 3);
            float f4 = __shfl_sync(0xffffffffu, dv, t + 4);
            float f5 = __shfl_sync(0xffffffffu, dv, t + 5);
            float f6 = __shfl_sync(0xffffffffu, dv, t + 6);
            float f7 = __shfl_sync(0xffffffffu, dv, t + 7);
            float2 v0 = __half22float2(__ldg(&h[(size_t)s0 * 32 + lane]));
            float2 v1 = __half22float2(__ldg(&h[(size_t)s1 * 32 + lane]));
            float2 v2 = __half22float2(__ldg(&h[(size_t)s2 * 32 + lane]));
            float2 v3 = __half22float2(__ldg(&h[(size_t)s3 * 32 + lane]));
            float2 v4 = __half22float2(__ldg(&h[(size_t)s4 * 32 + lane]));
            float2 v5 = __half22float2(__ldg(&h[(size_t)s5 * 32 + lane]));
            float2 v6 = __half22float2(__ldg(&h[(size_t)s6 * 32 + lane]));
            float2 v7 = __half22float2(__ldg(&h[(size_t)s7 * 32 + lane]));
            acc.x = fmaf(f0, v0.x, fmaf(f1, v1.x, fmaf(f2, v2.x, fmaf(f3, v3.x, acc.x))));
            acc.x = fmaf(f4, v4.x, fmaf(f5, v5.x, fmaf(f6, v6.x, fmaf(f7, v7.x, acc.x))));
            acc.y = fmaf(f0, v0.y, fmaf(f1, v1.y, fmaf(f2, v2.y, fmaf(f3, v3.y, acc.y))));
            acc.y = fmaf(f4, v4.y, fmaf(f5, v5.y, fmaf(f6, v6.y, fmaf(f7, v7.y, acc.y))));
        }
        j += cnt;
    }
    float w = __ldg(&g_dinv[node]);
    float2 b = ((const float2*)b2)[lane];
    ((float2*)out)[(size_t)node * 32 + lane] =
        make_float2(acc.x * w + b.x, acc.y * w + b.y);
}

// ---------------------------------------------------------------------------
extern "C" void kernel_launch(void* const* d_in, const int* in_sizes, int n_in,
                              void* d_out, int out_size) {
    const void*  eidx = d_in[0];
    const float* x    = (const float*)d_in[1];
    const float* W1   = (const float*)d_in[2];
    const float* b1   = (const float*)d_in[3];
    const float* W2   = (const float*)d_in[4];
    const float* b2   = (const float*)d_in[5];
    float* out = (float*)d_out;

    const int E = in_sizes[0] / 2;
    const int N = in_sizes[1] / NF1;

    __half *p_h1, *p_a1, *p_h2;
    float  *p_dinv;
    cudaGetSymbolAddress((void**)&p_h1,   g_h1);
    cudaGetSymbolAddress((void**)&p_a1,   g_a1);
    cudaGetSymbolAddress((void**)&p_h2,   g_h2);
    cudaGetSymbolAddress((void**)&p_dinv, g_dinv);

    static bool attr_done = false;
    if (!attr_done) {
        cudaFuncSetAttribute(gemm1_fp16, cudaFuncAttributeMaxDynamicSharedMemorySize, G1_SMEM);
        cudaFuncSetAttribute(gemm2_fp16, cudaFuncAttributeMaxDynamicSharedMemorySize, G2_SMEM);
        attr_done = true;
    }

    const int nb = (N + SCAN_ELEMS - 1) / SCAN_ELEMS;
    const int nscan = E < 2048 ? E : 2048;
    const int initN = (N > NF1 * NF1) ? N : NF1 * NF1;

    cudaStream_t s1;
    cudaStreamCreateWithFlags(&s1, cudaStreamNonBlocking);
    cudaEvent_t eFork, eG1;
    cudaEventCreateWithFlags(&eFork, cudaEventDisableTiming);
    cudaEventCreateWithFlags(&eG1,   cudaEventDisableTiming);

    k_init<<<(initN + 255) / 256, 256>>>((const long long*)eidx, nscan, N, W1, W2);
    cudaEventRecord(eFork, 0);
    cudaStreamWaitEvent(s1, eFork, 0);

    // branch B (s1): gemm1 (UNSCALED h1)
    gemm1_fp16<<<(N + G1_BM - 1) / G1_BM, 256, G1_SMEM, s1>>>(x, p_h1, N);
    cudaEventRecord(eG1, s1);

    // branch A (default): CSR build
    k_deg<<<((E + 1) / 2 + 255) / 256, 256>>>(eidx, E);
    k_scanL<<<nb, 256>>>(N, E);
    k_scatter<<<((E + 1) / 2 + 255) / 256, 256>>>(E);

    // join
    cudaStreamWaitEvent(0, eG1, 0);
    k_agg1<<<(N + 7) / 8, 256>>>(b1, N);
    gemm2_fp16<<<(N + G2_BM - 1) / G2_BM, 256, G2_SMEM>>>(p_a1, p_h2, p_dinv, N);
    k_agg2<<<(N + 7) / 8, 256>>>(b2, out, N);

    cudaEventDestroy(eFork);
    cudaEventDestroy(eG1);
    cudaStreamDestroy(s1);
}

// round 15
// speedup vs baseline: 1.5119x; 1.5119x over previous
#include <cuda_runtime.h>
#include <cuda_fp16.h>
#include <cstdint>
#include <cstddef>

// ---------------------------------------------------------------------------
// GCN_21569325760838: 2-layer GCN. CSR-gather (masked x8), fp16 mma GEMMs
// (fp32 accum, full-K smem resident, 3 CTAs/SM), fp16 intermediates,
// 3-phase parallel scan (lookback scan REVERTED - R14 regression),
// fork-join overlap.
//   h1  = x @ W1                        (UNSCALED fp16)
//   a1  = relu(dinv[d]*(sum_s dinv[s]*h1[s] + dinv[d]*h1[d]) + b1)
//   hs2 = dinv[row] * (a1 @ W2)
//   out = dinv[d]*(sum hs2[s] + hs2[d]) + b2
// ---------------------------------------------------------------------------

#define NMAX 100000
#define EMAX 1600000
#define NF1  128
#define NF2  64
#define SCAN_ELEMS 1024

__device__ int    g_is64 = 1;
__device__ int    g_deg [NMAX];
__device__ int    g_off [NMAX + 1];
__device__ int    g_cur [NMAX];
__device__ int    g_csr [EMAX];
__device__ int    g_src32[EMAX];
__device__ int    g_dst32[EMAX];
__device__ int    g_bsum[128];
__device__ int    g_boff[128];
__device__ float  g_dinv[NMAX];
__device__ __half g_h1  [(size_t)NMAX * NF1];   // UNSCALED x@W1
__device__ __half g_a1  [(size_t)NMAX * NF1];
__device__ __half g_h2  [(size_t)NMAX * NF2];   // dinv-scaled a1@W2
__device__ __half g_w1t [NF1 * NF1];
__device__ __half g_w2t [NF2 * NF1];

// ---------------------------------------------------------------------------
__global__ void k_init(const long long* __restrict__ p, int nscan, int n,
                       const float* __restrict__ W1, const float* __restrict__ W2) {
    int i = blockIdx.x * blockDim.x + threadIdx.x;
    if (i < n) g_deg[i] = 0;
    if (i < nscan) {
        long long v = p[i];
        if (v < 0 || v >= (long long)n) g_is64 = 0;
    }
    if (i < NF1 * NF1) {
        int nn = i / NF1, k = i % NF1;
        g_w1t[i] = __float2half(W1[(size_t)k * NF1 + nn]);
    }
    if (i < NF2 * NF1) {
        int nn = i / NF1, k = i % NF1;
        g_w2t[i] = __float2half(W2[(size_t)k * NF2 + nn]);
    }
}

__global__ void k_deg(const void* __restrict__ eidx, int E) {
    int i = blockIdx.x * blockDim.x + threadIdx.x;
    int e0 = i * 2;
    if (e0 >= E) return;
    int s0, s1 = -1, d0, d1 = -1;
    if (g_is64) {
        const long long* p = (const long long*)eidx;
        if (e0 + 1 < E) {
            longlong2 sv = __ldg((const longlong2*)(p + e0));
            longlong2 dv = __ldg((const longlong2*)(p + E + e0));
            s0 = (int)sv.x; s1 = (int)sv.y;
            d0 = (int)dv.x; d1 = (int)dv.y;
        } else {
            s0 = (int)__ldg(p + e0);
            d0 = (int)__ldg(p + E + e0);
        }
    } else {
        const int* p = (const int*)eidx;
        if (e0 + 1 < E) {
            int2 sv = __ldg((const int2*)(p + e0));
            int2 dv = __ldg((const int2*)(p + E + e0));
            s0 = sv.x; s1 = sv.y;
            d0 = dv.x; d1 = dv.y;
        } else {
            s0 = __ldg(p + e0);
            d0 = __ldg(p + E + e0);
        }
    }
    g_src32[e0] = s0;
    g_dst32[e0] = d0;
    atomicAdd(&g_deg[d0], 1);
    if (s1 >= 0) {
        g_src32[e0 + 1] = s1;
        g_dst32[e0 + 1] = d1;
        atomicAdd(&g_deg[d1], 1);
    }
}

// ---------------------------------------------------------------------------
__global__ void k_scan1(int n) {
    __shared__ int red[256];
    const int t = threadIdx.x;
    int i0 = blockIdx.x * SCAN_ELEMS + t * 4;
    int s = 0;
    #pragma unroll
    for (int k = 0; k < 4; k++) {
        int i = i0 + k;
        if (i < n) s += g_deg[i];
    }
    red[t] = s;
    __syncthreads();
    #pragma unroll
    for (int st = 128; st > 0; st >>= 1) {
        if (t < st) red[t] += red[t + st];
        __syncthreads();
    }
    if (t == 0) g_bsum[blockIdx.x] = red[0];
}

__global__ void k_scan2(int nb) {
    __shared__ int sm[128];
    const int t = threadIdx.x;
    int v = (t < nb) ? g_bsum[t] : 0;
    sm[t] = v;
    __syncthreads();
    #pragma unroll
    for (int st = 1; st < 128; st <<= 1) {
        int u = (t >= st) ? sm[t - st] : 0;
        __syncthreads();
        sm[t] += u;
        __syncthreads();
    }
    g_boff[t] = sm[t] - v;
}

__global__ void k_scan3(int n, int E) {
    __shared__ int sm[256];
    const int t = threadIdx.x;
    const int i0 = blockIdx.x * SCAN_ELEMS + t * 4;
    int vals[4];
    int s = 0;
    #pragma unroll
    for (int k = 0; k < 4; k++) {
        int i = i0 + k;
        vals[k] = (i < n) ? g_deg[i] : 0;
        s += vals[k];
    }
    sm[t] = s;
    __syncthreads();
    #pragma unroll
    for (int st = 1; st < 256; st <<= 1) {
        int u = (t >= st) ? sm[t - st] : 0;
        __syncthreads();
        sm[t] += u;
        __syncthreads();
    }
    int base = g_boff[blockIdx.x] + sm[t] - s;
    #pragma unroll
    for (int k = 0; k < 4; k++) {
        int i = i0 + k;
        if (i < n) {
            g_off[i] = base;
            g_cur[i] = base;
            g_dinv[i] = rsqrtf((float)(vals[k] + 1));
            base += vals[k];
        }
    }
    if (blockIdx.x == 0 && t == 0) g_off[n] = E;
}

__global__ void k_scatter(int E) {
    int i = blockIdx.x * blockDim.x + threadIdx.x;
    int e0 = i * 2;
    if (e0 >= E) return;
    if (e0 + 1 < E) {
        int2 d = __ldg((const int2*)(g_dst32 + e0));
        int2 s = __ldg((const int2*)(g_src32 + e0));
        int p0 = atomicAdd(&g_cur[d.x], 1);
        g_csr[p0] = s.x;
        int p1 = atomicAdd(&g_cur[d.y], 1);
        g_csr[p1] = s.y;
    } else {
        int d = g_dst32[e0];
        int p0 = atomicAdd(&g_cur[d], 1);
        g_csr[p0] = g_src32[e0];
    }
}

// ---------------------------------------------------------------------------
// GEMM1: fp16 mma, FULL-K resident. C fp16 = A_f32[M,128] @ W1 (UNSCALED).
// Block 64x128, 8 warps, warp tile 32x32, dynamic smem, 3 CTAs/SM.
// ---------------------------------------------------------------------------
#define G1_BM 64
#define G1_BN 128
#define G1_ST (NF1 + 8)
#define G1_SMEM ((G1_BM + G1_BN) * G1_ST * 2)

__global__ void __launch_bounds__(256, 3)
gemm1_fp16(const float* __restrict__ A, __half* __restrict__ C, int M) {
    constexpr int BM = G1_BM, BN = G1_BN, K = NF1, ST = G1_ST;
    constexpr int WNUM = BN / 32;
    extern __shared__ __half smem[];
    __half* As = smem;
    __half* Bs = smem + BM * ST;

    const int tid  = threadIdx.x;
    const int lane = tid & 31;
    const int warp = tid >> 5;
    const int gid  = lane >> 2;
    const int tig  = lane & 3;
    const int wm   = (warp / WNUM) * 32;
    const int wn   = (warp % WNUM) * 32;
    const int row0 = blockIdx.x * BM;

    #pragma unroll
    for (int idx = tid; idx < BM * (K / 4); idx += 256) {
        int r = idx / (K / 4), c4 = (idx % (K / 4)) * 4;
        float4 v = make_float4(0.f, 0.f, 0.f, 0.f);
        if (row0 + r < M)
            v = *(const float4*)(A + (size_t)(row0 + r) * K + c4);
        uint2 o;
        *(__half2*)&o.x = __floats2half2_rn(v.x, v.y);
        *(__half2*)&o.y = __floats2half2_rn(v.z, v.w);
        *(uint2*)&As[r * ST + c4] = o;
    }
    #pragma unroll
    for (int idx = tid; idx < BN * (K / 4); idx += 256) {
        int n = idx / (K / 4), c4 = (idx % (K / 4)) * 4;
        *(uint2*)&Bs[n * ST + c4] = *(const uint2*)(g_w1t + (size_t)n * K + c4);
    }
    __syncthreads();

    float acc[2][4][4];
    #pragma unroll
    for (int mt = 0; mt < 2; mt++)
        #pragma unroll
        for (int nt = 0; nt < 4; nt++)
            #pragma unroll
            for (int i = 0; i < 4; i++) acc[mt][nt][i] = 0.f;

    #pragma unroll
    for (int ks = 0; ks < K / 16; ks++) {
        const int kk = ks * 16;
        uint32_t af[2][4];
        #pragma unroll
        for (int mt = 0; mt < 2; mt++) {
            int rb = wm + mt * 16 + gid;
            af[mt][0] = *(const uint32_t*)&As[rb * ST + kk + 2 * tig];
            af[mt][1] = *(const uint32_t*)&As[(rb + 8) * ST + kk + 2 * tig];
            af[mt][2] = *(const uint32_t*)&As[rb * ST + kk + 2 * tig + 8];
            af[mt][3] = *(const uint32_t*)&As[(rb + 8) * ST + kk + 2 * tig + 8];
        }
        uint32_t bf[4][2];
        #pragma unroll
        for (int nt = 0; nt < 4; nt++) {
            int cb = wn + nt * 8 + gid;
            bf[nt][0] = *(const uint32_t*)&Bs[cb * ST + kk + 2 * tig];
            bf[nt][1] = *(const uint32_t*)&Bs[cb * ST + kk + 2 * tig + 8];
        }
        #pragma unroll
        for (int mt = 0; mt < 2; mt++)
            #pragma unroll
            for (int nt = 0; nt < 4; nt++) {
                asm volatile(
                    "mma.sync.aligned.m16n8k16.row.col.f32.f16.f16.f32 "
                    "{%0,%1,%2,%3}, {%4,%5,%6,%7}, {%8,%9}, {%0,%1,%2,%3};\n"
                    : "+f"(acc[mt][nt][0]), "+f"(acc[mt][nt][1]),
                      "+f"(acc[mt][nt][2]), "+f"(acc[mt][nt][3])
                    : "r"(af[mt][0]), "r"(af[mt][1]),
                      "r"(af[mt][2]), "r"(af[mt][3]),
                      "r"(bf[nt][0]), "r"(bf[nt][1]));
            }
    }

    #pragma unroll
    for (int mt = 0; mt < 2; mt++) {
        int r0 = row0 + wm + mt * 16 + gid;
        int r1 = r0 + 8;
        #pragma unroll
        for (int nt = 0; nt < 4; nt++) {
            int col = wn + nt * 8 + 2 * tig;
            if (r0 < M)
                *(__half2*)(C + (size_t)r0 * BN + col) =
                    __floats2half2_rn(acc[mt][nt][0], acc[mt][nt][1]);
            if (r1 < M)
                *(__half2*)(C + (size_t)r1 * BN + col) =
                    __floats2half2_rn(acc[mt][nt][2], acc[mt][nt][3]);
        }
    }
}

// ---------------------------------------------------------------------------
// GEMM2: fp16 mma, FULL-K resident. C fp16 = rowscale*(A_f16 @ W2).
// Block 128x64, 8 warps, warp tile 32x32, dynamic smem, 3 CTAs/SM.
// ---------------------------------------------------------------------------
#define G2_BM 128
#define G2_BN 64
#define G2_ST (NF1 + 8)
#define G2_SMEM ((G2_BM + G2_BN) * G2_ST * 2)

__global__ void __launch_bounds__(256, 3)
gemm2_fp16(const __half* __restrict__ A, __half* __restrict__ C,
           const float* __restrict__ rowscale, int M) {
    constexpr int BM = G2_BM, BN = G2_BN, K = NF1, ST = G2_ST;
    constexpr int WNUM = BN / 32;
    extern __shared__ __half smem[];
    __half* As = smem;
    __half* Bs = smem + BM * ST;

    const int tid  = threadIdx.x;
    const int lane = tid & 31;
    const int warp = tid >> 5;
    const int gid  = lane >> 2;
    const int tig  = lane & 3;
    const int wm   = (warp / WNUM) * 32;
    const int wn   = (warp % WNUM) * 32;
    const int row0 = blockIdx.x * BM;

    #pragma unroll
    for (int idx = tid; idx < BM * (K / 4); idx += 256) {
        int r = idx / (K / 4), c4 = (idx % (K / 4)) * 4;
        uint2 v = make_uint2(0u, 0u);
        if (row0 + r < M)
            v = *(const uint2*)(A + (size_t)(row0 + r) * K + c4);
        *(uint2*)&As[r * ST + c4] = v;
    }
    #pragma unroll
    for (int idx = tid; idx < BN * (K / 4); idx += 256) {
        int n = idx / (K / 4), c4 = (idx % (K / 4)) * 4;
        *(uint2*)&Bs[n * ST + c4] = *(const uint2*)(g_w2t + (size_t)n * K + c4);
    }
    __syncthreads();

    float acc[2][4][4];
    #pragma unroll
    for (int mt = 0; mt < 2; mt++)
        #pragma unroll
        for (int nt = 0; nt < 4; nt++)
            #pragma unroll
            for (int i = 0; i < 4; i++) acc[mt][nt][i] = 0.f;

    #pragma unroll
    for (int ks = 0; ks < K / 16; ks++) {
        const int kk = ks * 16;
        uint32_t af[2][4];
        #pragma unroll
        for (int mt = 0; mt < 2; mt++) {
            int rb = wm + mt * 16 + gid;
            af[mt][0] = *(const uint32_t*)&As[rb * ST + kk + 2 * tig];
            af[mt][1] = *(const uint32_t*)&As[(rb + 8) * ST + kk + 2 * tig];
            af[mt][2] = *(const uint32_t*)&As[rb * ST + kk + 2 * tig + 8];
            af[mt][3] = *(const uint32_t*)&As[(rb + 8) * ST + kk + 2 * tig + 8];
        }
        uint32_t bf[4][2];
        #pragma unroll
        for (int nt = 0; nt < 4; nt++) {
            int cb = wn + nt * 8 + gid;
            bf[nt][0] = *(const uint32_t*)&Bs[cb * ST + kk + 2 * tig];
            bf[nt][1] = *(const uint32_t*)&Bs[cb * ST + kk + 2 * tig + 8];
        }
        #pragma unroll
        for (int mt = 0; mt < 2; mt++)
            #pragma unroll
            for (int nt = 0; nt < 4; nt++) {
                asm volatile(
                    "mma.sync.aligned.m16n8k16.row.col.f32.f16.f16.f32 "
                    "{%0,%1,%2,%3}, {%4,%5,%6,%7}, {%8,%9}, {%0,%1,%2,%3};\n"
                    : "+f"(acc[mt][nt][0]), "+f"(acc[mt][nt][1]),
                      "+f"(acc[mt][nt][2]), "+f"(acc[mt][nt][3])
                    : "r"(af[mt][0]), "r"(af[mt][1]),
                      "r"(af[mt][2]), "r"(af[mt][3]),
                      "r"(bf[nt][0]), "r"(bf[nt][1]));
            }
    }

    #pragma unroll
    for (int mt = 0; mt < 2; mt++) {
        int r0 = row0 + wm + mt * 16 + gid;
        int r1 = r0 + 8;
        #pragma unroll
        for (int nt = 0; nt < 4; nt++) {
            int col = wn + nt * 8 + 2 * tig;
            if (r0 < M) {
                float sc = rowscale[r0];
                *(__half2*)(C + (size_t)r0 * BN + col) =
                    __floats2half2_rn(acc[mt][nt][0] * sc, acc[mt][nt][1] * sc);
            }
            if (r1 < M) {
                float sc = rowscale[r1];
                *(__half2*)(C + (size_t)r1 * BN + col) =
                    __floats2half2_rn(acc[mt][nt][2] * sc, acc[mt][nt][3] * sc);
            }
        }
    }
}

// ---------------------------------------------------------------------------
// Layer-1 aggregation over UNSCALED h1. Masked full-width x8 loop.
__global__ void k_agg1(const float* __restrict__ b1, int n) {
    int node = blockIdx.x * (blockDim.x >> 5) + (threadIdx.x >> 5);
    if (node >= n) return;
    int lane = threadIdx.x & 31;

    const uint2* h = (const uint2*)g_h1;
    const float w = __ldg(&g_dinv[node]);

    uint2 sv = __ldg(&h[(size_t)node * 32 + lane]);
    float2 lo = __half22float2(*(__half2*)&sv.x);
    float2 hi = __half22float2(*(__half2*)&sv.y);
    float4 acc = make_float4(w * lo.x, w * lo.y, w * hi.x, w * hi.y);

    int j = g_off[node];
    const int jend = g_off[node + 1];
    while (j < jend) {
        int cnt = min(32, jend - j);
        int sidx = 0; float dv = 0.f;
        if (lane < cnt) { sidx = __ldg(&g_csr[j + lane]); dv = __ldg(&g_dinv[sidx]); }
        for (int t = 0; t < cnt; t += 8) {
            int s0 = __shfl_sync(0xffffffffu, sidx, t);
            int s1 = __shfl_sync(0xffffffffu, sidx, t + 1);
            int s2 = __shfl_sync(0xffffffffu, sidx, t + 2);
            int s3 = __shfl_sync(0xffffffffu, sidx, t + 3);
            int s4 = __shfl_sync(0xffffffffu, sidx, t + 4);
            int s5 = __shfl_sync(0xffffffffu, sidx, t + 5);
            int s6 = __shfl_sync(0xffffffffu, sidx, t + 6);
            int s7 = __shfl_sync(0xffffffffu, sidx, t + 7);
            float f0 = __shfl_sync(0xffffffffu, dv, t);
            float f1 = __shfl_sync(0xffffffffu, dv, t + 1);
            float f2 = __shfl_sync(0xffffffffu, dv, t + 2);
            float f3 = __shfl_sync(0xffffffffu, dv, t + 3);
            float f4 = __shfl_sync(0xffffffffu, dv, t + 4);
            float f5 = __shfl_sync(0xffffffffu, dv, t + 5);
            float f6 = __shfl_sync(0xffffffffu, dv, t + 6);
            float f7 = __shfl_sync(0xffffffffu, dv, t + 7);
            uint2 v0 = __ldg(&h[(size_t)s0 * 32 + lane]);
            uint2 v1 = __ldg(&h[(size_t)s1 * 32 + lane]);
            uint2 v2 = __ldg(&h[(size_t)s2 * 32 + lane]);
            uint2 v3 = __ldg(&h[(size_t)s3 * 32 + lane]);
            uint2 v4 = __ldg(&h[(size_t)s4 * 32 + lane]);
            uint2 v5 = __ldg(&h[(size_t)s5 * 32 + lane]);
            uint2 v6 = __ldg(&h[(size_t)s6 * 32 + lane]);
            uint2 v7 = __ldg(&h[(size_t)s7 * 32 + lane]);
            float2 p0 = __half22float2(*(__half2*)&v0.x), q0 = __half22float2(*(__half2*)&v0.y);
            float2 p1 = __half22float2(*(__half2*)&v1.x), q1 = __half22float2(*(__half2*)&v1.y);
            float2 p2 = __half22float2(*(__half2*)&v2.x), q2 = __half22float2(*(__half2*)&v2.y);
            float2 p3 = __half22float2(*(__half2*)&v3.x), q3 = __half22float2(*(__half2*)&v3.y);
            float2 p4 = __half22float2(*(__half2*)&v4.x), q4 = __half22float2(*(__half2*)&v4.y);
            float2 p5 = __half22float2(*(__half2*)&v5.x), q5 = __half22float2(*(__half2*)&v5.y);
            float2 p6 = __half22float2(*(__half2*)&v6.x), q6 = __half22float2(*(__half2*)&v6.y);
            float2 p7 = __half22float2(*(__half2*)&v7.x), q7 = __half22float2(*(__half2*)&v7.y);
            acc.x = fmaf(f0, p0.x, fmaf(f1, p1.x, fmaf(f2, p2.x, fmaf(f3, p3.x, acc.x))));
            acc.x = fmaf(f4, p4.x, fmaf(f5, p5.x, fmaf(f6, p6.x, fmaf(f7, p7.x, acc.x))));
            acc.y = fmaf(f0, p0.y, fmaf(f1, p1.y, fmaf(f2, p2.y, fmaf(f3, p3.y, acc.y))));
            acc.y = fmaf(f4, p4.y, fmaf(f5, p5.y, fmaf(f6, p6.y, fmaf(f7, p7.y, acc.y))));
            acc.z = fmaf(f0, q0.x, fmaf(f1, q1.x, fmaf(f2, q2.x, fmaf(f3, q3.x, acc.z))));
            acc.z = fmaf(f4, q4.x, fmaf(f5, q5.x, fmaf(f6, q6.x, fmaf(f7, q7.x, acc.z))));
            acc.w = fmaf(f0, q0.y, fmaf(f1, q1.y, fmaf(f2, q2.y, fmaf(f3, q3.y, acc.w))));
            acc.w = fmaf(f4, q4.y, fmaf(f5, q5.y, fmaf(f6, q6.y, fmaf(f7, q7.y, acc.w))));
        }
        j += cnt;
    }
    float4 b = ((const float4*)b1)[lane];
    uint2 o;
    *(__half2*)&o.x = __floats2half2_rn(fmaxf(acc.x * w + b.x, 0.f),
                                        fmaxf(acc.y * w + b.y, 0.f));
    *(__half2*)&o.y = __floats2half2_rn(fmaxf(acc.z * w + b.z, 0.f),
                                        fmaxf(acc.w * w + b.w, 0.f));
    ((uint2*)g_a1)[(size_t)node * 32 + lane] = o;
}

// Layer-2 aggregation over pre-scaled h2. Masked full-width x8; fp32 out.
__global__ void k_agg2(const float* __restrict__ b2, float* __restrict__ out, int n) {
    int node = blockIdx.x * (blockDim.x >> 5) + (threadIdx.x >> 5);
    if (node >= n) return;
    int lane = threadIdx.x & 31;

    const __half2* h = (const __half2*)g_h2;
    float2 acc = __half22float2(__ldg(&h[(size_t)node * 32 + lane]));
    int j = g_off[node];
    const int jend = g_off[node + 1];
    while (j < jend) {
        int cnt = min(32, jend - j);
        int sidx = 0; float dv = 0.f;
        if (lane < cnt) { sidx = __ldg(&g_csr[j + lane]); dv = 1.0f; }
        for (int t = 0; t < cnt; t += 8) {
            int s0 = __shfl_sync(0xffffffffu, sidx, t);
            int s1 = __shfl_sync(0xffffffffu, sidx, t + 1);
            int s2 = __shfl_sync(0xffffffffu, sidx, t + 2);
            int s3 = __shfl_sync(0xffffffffu, sidx, t + 3);
            int s4 = __shfl_sync(0xffffffffu, sidx, t + 4);
            int s5 = __shfl_sync(0xffffffffu, sidx, t + 5);
            int s6 = __shfl_sync(0xffffffffu, sidx, t + 6);
            int s7 = __shfl_sync(0xffffffffu, sidx, t + 7);
            float f0 = __shfl_sync(0xffffffffu, dv, t);
            float f1 = __shfl_sync(0xffffffffu, dv, t + 1);
            float f2 = __shfl_sync(0xffffffffu, dv, t + 2);
            float f3 = __shfl_sync(0xffffffffu, dv, t + 3);
            float f4 = __shfl_sync(0xffffffffu, dv, t + 4);
            float f5 = __shfl_sync(0xffffffffu, dv, t + 5);
            float f6 = __shfl_sync(0xffffffffu, dv, t + 6);
            float f7 = __shfl_sync(0xffffffffu, dv, t + 7);
            float2 v0 = __half22float2(__ldg(&h[(size_t)s0 * 32 + lane]));
            float2 v1 = __half22float2(__ldg(&h[(size_t)s1 * 32 + lane]));
            float2 v2 = __half22float2(__ldg(&h[(size_t)s2 * 32 + lane]));
            float2 v3 = __half22float2(__ldg(&h[(size_t)s3 * 32 + lane]));
            float2 v4 = __half22float2(__ldg(&h[(size_t)s4 * 32 + lane]));
            float2 v5 = __half22float2(__ldg(&h[(size_t)s5 * 32 + lane]));
            float2 v6 = __half22float2(__ldg(&h[(size_t)s6 * 32 + lane]));
            float2 v7 = __half22float2(__ldg(&h[(size_t)s7 * 32 + lane]));
            acc.x = fmaf(f0, v0.x, fmaf(f1, v1.x, fmaf(f2, v2.x, fmaf(f3, v3.x, acc.x))));
            acc.x = fmaf(f4, v4.x, fmaf(f5, v5.x, fmaf(f6, v6.x, fmaf(f7, v7.x, acc.x))));
            acc.y = fmaf(f0, v0.y, fmaf(f1, v1.y, fmaf(f2, v2.y, fmaf(f3, v3.y, acc.y))));
            acc.y = fmaf(f4, v4.y, fmaf(f5, v5.y, fmaf(f6, v6.y, fmaf(f7, v7.y, acc.y))));
        }
        j += cnt;
    }
    float w = __ldg(&g_dinv[node]);
    float2 b = ((const float2*)b2)[lane];
    ((float2*)out)[(size_t)node * 32 + lane] =
        make_float2(acc.x * w + b.x, acc.y * w + b.y);
}

// ---------------------------------------------------------------------------
extern "C" void kernel_launch(void* const* d_in, const int* in_sizes, int n_in,
                              void* d_out, int out_size) {
    const void*  eidx = d_in[0];
    const float* x    = (const float*)d_in[1];
    const float* W1   = (const float*)d_in[2];
    const float* b1   = (const float*)d_in[3];
    const float* W2   = (const float*)d_in[4];
    const float* b2   = (const float*)d_in[5];
    float* out = (float*)d_out;

    const int E = in_sizes[0] / 2;
    const int N = in_sizes[1] / NF1;

    __half *p_h1, *p_a1, *p_h2;
    float  *p_dinv;
    cudaGetSymbolAddress((void**)&p_h1,   g_h1);
    cudaGetSymbolAddress((void**)&p_a1,   g_a1);
    cudaGetSymbolAddress((void**)&p_h2,   g_h2);
    cudaGetSymbolAddress((void**)&p_dinv, g_dinv);

    static bool attr_done = false;
    if (!attr_done) {
        cudaFuncSetAttribute(gemm1_fp16, cudaFuncAttributeMaxDynamicSharedMemorySize, G1_SMEM);
        cudaFuncSetAttribute(gemm2_fp16, cudaFuncAttributeMaxDynamicSharedMemorySize, G2_SMEM);
        attr_done = true;
    }

    const int nb = (N + SCAN_ELEMS - 1) / SCAN_ELEMS;
    const int nscan = E < 2048 ? E : 2048;
    const int initN = (N > NF1 * NF1) ? N : NF1 * NF1;

    cudaStream_t s1;
    cudaStreamCreateWithFlags(&s1, cudaStreamNonBlocking);
    cudaEvent_t eFork, eG1;
    cudaEventCreateWithFlags(&eFork, cudaEventDisableTiming);
    cudaEventCreateWithFlags(&eG1,   cudaEventDisableTiming);

    k_init<<<(initN + 255) / 256, 256>>>((const long long*)eidx, nscan, N, W1, W2);
    cudaEventRecord(eFork, 0);
    cudaStreamWaitEvent(s1, eFork, 0);

    // branch B (s1): gemm1 (UNSCALED h1)
    gemm1_fp16<<<(N + G1_BM - 1) / G1_BM, 256, G1_SMEM, s1>>>(x, p_h1, N);
    cudaEventRecord(eG1, s1);

    // branch A (default): CSR build (3-phase scan)
    k_deg<<<((E + 1) / 2 + 255) / 256, 256>>>(eidx, E);
    k_scan1<<<nb, 256>>>(N);
    k_scan2<<<1, 128>>>(nb);
    k_scan3<<<nb, 256>>>(N, E);
    k_scatter<<<((E + 1) / 2 + 255) / 256, 256>>>(E);

    // join
    cudaStreamWaitEvent(0, eG1, 0);
    k_agg1<<<(N + 7) / 8, 256>>>(b1, N);
    gemm2_fp16<<<(N + G2_BM - 1) / G2_BM, 256, G2_SMEM>>>(p_a1, p_h2, p_dinv, N);
    k_agg2<<<(N + 7) / 8, 256>>>(b2, out, N);

    cudaEventDestroy(eFork);
    cudaEventDestroy(eG1);
    cudaStreamDestroy(s1);
}

// round 16
// speedup vs baseline: 1.5679x; 1.0370x over previous
#include <cuda_runtime.h>
#include <cuda_fp16.h>
#include <cstdint>
#include <cstddef>

// ---------------------------------------------------------------------------
// GCN_21569325760838: 2-layer GCN. CSR-gather (masked x8), fp16 mma GEMMs
// (fp32 accum, full-K smem resident, 3 CTAs/SM), fp16 intermediates,
// 3-phase scan, x4-wide edge pass, 16-lane sub-warp agg2.
//   h1  = x @ W1                        (UNSCALED fp16)
//   a1  = relu(dinv[d]*(sum_s dinv[s]*h1[s] + dinv[d]*h1[d]) + b1)
//   hs2 = dinv[row] * (a1 @ W2)
//   out = dinv[d]*(sum hs2[s] + hs2[d]) + b2
// ---------------------------------------------------------------------------

#define NMAX 100000
#define EMAX 1600000
#define NF1  128
#define NF2  64
#define SCAN_ELEMS 1024

__device__ int    g_is64 = 1;
__device__ int    g_deg [NMAX];
__device__ int    g_off [NMAX + 1];
__device__ int    g_cur [NMAX];
__device__ int    g_csr [EMAX];
__device__ int    g_src32[EMAX];
__device__ int    g_dst32[EMAX];
__device__ int    g_bsum[128];
__device__ int    g_boff[128];
__device__ float  g_dinv[NMAX];
__device__ __half g_h1  [(size_t)NMAX * NF1];   // UNSCALED x@W1
__device__ __half g_a1  [(size_t)NMAX * NF1];
__device__ __half g_h2  [(size_t)NMAX * NF2];   // dinv-scaled a1@W2
__device__ __half g_w1t [NF1 * NF1];
__device__ __half g_w2t [NF2 * NF1];

// ---------------------------------------------------------------------------
__global__ void k_init(const long long* __restrict__ p, int nscan, int n,
                       const float* __restrict__ W1, const float* __restrict__ W2) {
    int i = blockIdx.x * blockDim.x + threadIdx.x;
    if (i < n) g_deg[i] = 0;
    if (i < nscan) {
        long long v = p[i];
        if (v < 0 || v >= (long long)n) g_is64 = 0;
    }
    if (i < NF1 * NF1) {
        int nn = i / NF1, k = i % NF1;
        g_w1t[i] = __float2half(W1[(size_t)k * NF1 + nn]);
    }
    if (i < NF2 * NF1) {
        int nn = i / NF1, k = i % NF1;
        g_w2t[i] = __float2half(W2[(size_t)k * NF2 + nn]);
    }
}

// Degree histogram + compact int32 copy; 4 edges per thread.
__global__ void k_deg(const void* __restrict__ eidx, int E) {
    int i = blockIdx.x * blockDim.x + threadIdx.x;
    int e0 = i * 4;
    if (e0 >= E) return;
    int s[4], d[4];
    int cnt = min(4, E - e0);
    if (g_is64) {
        const long long* p = (const long long*)eidx;
        if (cnt == 4) {
            longlong2 sa = __ldg((const longlong2*)(p + e0));
            longlong2 sb = __ldg((const longlong2*)(p + e0 + 2));
            longlong2 da = __ldg((const longlong2*)(p + E + e0));
            longlong2 db = __ldg((const longlong2*)(p + E + e0 + 2));
            s[0] = (int)sa.x; s[1] = (int)sa.y; s[2] = (int)sb.x; s[3] = (int)sb.y;
            d[0] = (int)da.x; d[1] = (int)da.y; d[2] = (int)db.x; d[3] = (int)db.y;
        } else {
            for (int k = 0; k < cnt; k++) {
                s[k] = (int)__ldg(p + e0 + k);
                d[k] = (int)__ldg(p + E + e0 + k);
            }
        }
    } else {
        const int* p = (const int*)eidx;
        if (cnt == 4) {
            int4 sv = __ldg((const int4*)(p + e0));
            int4 dv = __ldg((const int4*)(p + E + e0));
            s[0] = sv.x; s[1] = sv.y; s[2] = sv.z; s[3] = sv.w;
            d[0] = dv.x; d[1] = dv.y; d[2] = dv.z; d[3] = dv.w;
        } else {
            for (int k = 0; k < cnt; k++) {
                s[k] = __ldg(p + e0 + k);
                d[k] = __ldg(p + E + e0 + k);
            }
        }
    }
    if (cnt == 4) {
        *(int4*)(g_src32 + e0) = make_int4(s[0], s[1], s[2], s[3]);
        *(int4*)(g_dst32 + e0) = make_int4(d[0], d[1], d[2], d[3]);
    } else {
        for (int k = 0; k < cnt; k++) {
            g_src32[e0 + k] = s[k];
            g_dst32[e0 + k] = d[k];
        }
    }
    for (int k = 0; k < cnt; k++) atomicAdd(&g_deg[d[k]], 1);
}

// ---------------------------------------------------------------------------
__global__ void k_scan1(int n) {
    __shared__ int red[256];
    const int t = threadIdx.x;
    int i0 = blockIdx.x * SCAN_ELEMS + t * 4;
    int s = 0;
    #pragma unroll
    for (int k = 0; k < 4; k++) {
        int i = i0 + k;
        if (i < n) s += g_deg[i];
    }
    red[t] = s;
    __syncthreads();
    #pragma unroll
    for (int st = 128; st > 0; st >>= 1) {
        if (t < st) red[t] += red[t + st];
        __syncthreads();
    }
    if (t == 0) g_bsum[blockIdx.x] = red[0];
}

__global__ void k_scan2(int nb) {
    __shared__ int sm[128];
    const int t = threadIdx.x;
    int v = (t < nb) ? g_bsum[t] : 0;
    sm[t] = v;
    __syncthreads();
    #pragma unroll
    for (int st = 1; st < 128; st <<= 1) {
        int u = (t >= st) ? sm[t - st] : 0;
        __syncthreads();
        sm[t] += u;
        __syncthreads();
    }
    g_boff[t] = sm[t] - v;
}

__global__ void k_scan3(int n, int E) {
    __shared__ int sm[256];
    const int t = threadIdx.x;
    const int i0 = blockIdx.x * SCAN_ELEMS + t * 4;
    int vals[4];
    int s = 0;
    #pragma unroll
    for (int k = 0; k < 4; k++) {
        int i = i0 + k;
        vals[k] = (i < n) ? g_deg[i] : 0;
        s += vals[k];
    }
    sm[t] = s;
    __syncthreads();
    #pragma unroll
    for (int st = 1; st < 256; st <<= 1) {
        int u = (t >= st) ? sm[t - st] : 0;
        __syncthreads();
        sm[t] += u;
        __syncthreads();
    }
    int base = g_boff[blockIdx.x] + sm[t] - s;
    #pragma unroll
    for (int k = 0; k < 4; k++) {
        int i = i0 + k;
        if (i < n) {
            g_off[i] = base;
            g_cur[i] = base;
            g_dinv[i] = rsqrtf((float)(vals[k] + 1));
            base += vals[k];
        }
    }
    if (blockIdx.x == 0 && t == 0) g_off[n] = E;
}

// Scatter; 4 edges per thread (int4 loads).
__global__ void k_scatter(int E) {
    int i = blockIdx.x * blockDim.x + threadIdx.x;
    int e0 = i * 4;
    if (e0 >= E) return;
    int cnt = min(4, E - e0);
    if (cnt == 4) {
        int4 d = __ldg((const int4*)(g_dst32 + e0));
        int4 s = __ldg((const int4*)(g_src32 + e0));
        int p0 = atomicAdd(&g_cur[d.x], 1); g_csr[p0] = s.x;
        int p1 = atomicAdd(&g_cur[d.y], 1); g_csr[p1] = s.y;
        int p2 = atomicAdd(&g_cur[d.z], 1); g_csr[p2] = s.z;
        int p3 = atomicAdd(&g_cur[d.w], 1); g_csr[p3] = s.w;
    } else {
        for (int k = 0; k < cnt; k++) {
            int d = g_dst32[e0 + k];
            int p0 = atomicAdd(&g_cur[d], 1);
            g_csr[p0] = g_src32[e0 + k];
        }
    }
}

// ---------------------------------------------------------------------------
// GEMM1: fp16 mma, FULL-K resident. C fp16 = A_f32[M,128] @ W1 (UNSCALED).
// Block 64x128, 8 warps, warp tile 32x32, dynamic smem, 3 CTAs/SM.
// ---------------------------------------------------------------------------
#define G1_BM 64
#define G1_BN 128
#define G1_ST (NF1 + 8)
#define G1_SMEM ((G1_BM + G1_BN) * G1_ST * 2)

__global__ void __launch_bounds__(256, 3)
gemm1_fp16(const float* __restrict__ A, __half* __restrict__ C, int M) {
    constexpr int BM = G1_BM, BN = G1_BN, K = NF1, ST = G1_ST;
    constexpr int WNUM = BN / 32;
    extern __shared__ __half smem[];
    __half* As = smem;
    __half* Bs = smem + BM * ST;

    const int tid  = threadIdx.x;
    const int lane = tid & 31;
    const int warp = tid >> 5;
    const int gid  = lane >> 2;
    const int tig  = lane & 3;
    const int wm   = (warp / WNUM) * 32;
    const int wn   = (warp % WNUM) * 32;
    const int row0 = blockIdx.x * BM;

    #pragma unroll
    for (int idx = tid; idx < BM * (K / 4); idx += 256) {
        int r = idx / (K / 4), c4 = (idx % (K / 4)) * 4;
        float4 v = make_float4(0.f, 0.f, 0.f, 0.f);
        if (row0 + r < M)
            v = *(const float4*)(A + (size_t)(row0 + r) * K + c4);
        uint2 o;
        *(__half2*)&o.x = __floats2half2_rn(v.x, v.y);
        *(__half2*)&o.y = __floats2half2_rn(v.z, v.w);
        *(uint2*)&As[r * ST + c4] = o;
    }
    #pragma unroll
    for (int idx = tid; idx < BN * (K / 4); idx += 256) {
        int n = idx / (K / 4), c4 = (idx % (K / 4)) * 4;
        *(uint2*)&Bs[n * ST + c4] = *(const uint2*)(g_w1t + (size_t)n * K + c4);
    }
    __syncthreads();

    float acc[2][4][4];
    #pragma unroll
    for (int mt = 0; mt < 2; mt++)
        #pragma unroll
        for (int nt = 0; nt < 4; nt++)
            #pragma unroll
            for (int i = 0; i < 4; i++) acc[mt][nt][i] = 0.f;

    #pragma unroll
    for (int ks = 0; ks < K / 16; ks++) {
        const int kk = ks * 16;
        uint32_t af[2][4];
        #pragma unroll
        for (int mt = 0; mt < 2; mt++) {
            int rb = wm + mt * 16 + gid;
            af[mt][0] = *(const uint32_t*)&As[rb * ST + kk + 2 * tig];
            af[mt][1] = *(const uint32_t*)&As[(rb + 8) * ST + kk + 2 * tig];
            af[mt][2] = *(const uint32_t*)&As[rb * ST + kk + 2 * tig + 8];
            af[mt][3] = *(const uint32_t*)&As[(rb + 8) * ST + kk + 2 * tig + 8];
        }
        uint32_t bf[4][2];
        #pragma unroll
        for (int nt = 0; nt < 4; nt++) {
            int cb = wn + nt * 8 + gid;
            bf[nt][0] = *(const uint32_t*)&Bs[cb * ST + kk + 2 * tig];
            bf[nt][1] = *(const uint32_t*)&Bs[cb * ST + kk + 2 * tig + 8];
        }
        #pragma unroll
        for (int mt = 0; mt < 2; mt++)
            #pragma unroll
            for (int nt = 0; nt < 4; nt++) {
                asm volatile(
                    "mma.sync.aligned.m16n8k16.row.col.f32.f16.f16.f32 "
                    "{%0,%1,%2,%3}, {%4,%5,%6,%7}, {%8,%9}, {%0,%1,%2,%3};\n"
                    : "+f"(acc[mt][nt][0]), "+f"(acc[mt][nt][1]),
                      "+f"(acc[mt][nt][2]), "+f"(acc[mt][nt][3])
                    : "r"(af[mt][0]), "r"(af[mt][1]),
                      "r"(af[mt][2]), "r"(af[mt][3]),
                      "r"(bf[nt][0]), "r"(bf[nt][1]));
            }
    }

    #pragma unroll
    for (int mt = 0; mt < 2; mt++) {
        int r0 = row0 + wm + mt * 16 + gid;
        int r1 = r0 + 8;
        #pragma unroll
        for (int nt = 0; nt < 4; nt++) {
            int col = wn + nt * 8 + 2 * tig;
            if (r0 < M)
                *(__half2*)(C + (size_t)r0 * BN + col) =
                    __floats2half2_rn(acc[mt][nt][0], acc[mt][nt][1]);
            if (r1 < M)
                *(__half2*)(C + (size_t)r1 * BN + col) =
                    __floats2half2_rn(acc[mt][nt][2], acc[mt][nt][3]);
        }
    }
}

// ---------------------------------------------------------------------------
// GEMM2: fp16 mma, FULL-K resident. C fp16 = rowscale*(A_f16 @ W2).
// Block 128x64, 8 warps, warp tile 32x32, dynamic smem, 3 CTAs/SM.
// ---------------------------------------------------------------------------
#define G2_BM 128
#define G2_BN 64
#define G2_ST (NF1 + 8)
#define G2_SMEM ((G2_BM + G2_BN) * G2_ST * 2)

__global__ void __launch_bounds__(256, 3)
gemm2_fp16(const __half* __restrict__ A, __half* __restrict__ C,
           const float* __restrict__ rowscale, int M) {
    constexpr int BM = G2_BM, BN = G2_BN, K = NF1, ST = G2_ST;
    constexpr int WNUM = BN / 32;
    extern __shared__ __half smem[];
    __half* As = smem;
    __half* Bs = smem + BM * ST;

    const int tid  = threadIdx.x;
    const int lane = tid & 31;
    const int warp = tid >> 5;
    const int gid  = lane >> 2;
    const int tig  = lane & 3;
    const int wm   = (warp / WNUM) * 32;
    const int wn   = (warp % WNUM) * 32;
    const int row0 = blockIdx.x * BM;

    #pragma unroll
    for (int idx = tid; idx < BM * (K / 4); idx += 256) {
        int r = idx / (K / 4), c4 = (idx % (K / 4)) * 4;
        uint2 v = make_uint2(0u, 0u);
        if (row0 + r < M)
            v = *(const uint2*)(A + (size_t)(row0 + r) * K + c4);
        *(uint2*)&As[r * ST + c4] = v;
    }
    #pragma unroll
    for (int idx = tid; idx < BN * (K / 4); idx += 256) {
        int n = idx / (K / 4), c4 = (idx % (K / 4)) * 4;
        *(uint2*)&Bs[n * ST + c4] = *(const uint2*)(g_w2t + (size_t)n * K + c4);
    }
    __syncthreads();

    float acc[2][4][4];
    #pragma unroll
    for (int mt = 0; mt < 2; mt++)
        #pragma unroll
        for (int nt = 0; nt < 4; nt++)
            #pragma unroll
            for (int i = 0; i < 4; i++) acc[mt][nt][i] = 0.f;

    #pragma unroll
    for (int ks = 0; ks < K / 16; ks++) {
        const int kk = ks * 16;
        uint32_t af[2][4];
        #pragma unroll
        for (int mt = 0; mt < 2; mt++) {
            int rb = wm + mt * 16 + gid;
            af[mt][0] = *(const uint32_t*)&As[rb * ST + kk + 2 * tig];
            af[mt][1] = *(const uint32_t*)&As[(rb + 8) * ST + kk + 2 * tig];
            af[mt][2] = *(const uint32_t*)&As[rb * ST + kk + 2 * tig + 8];
            af[mt][3] = *(const uint32_t*)&As[(rb + 8) * ST + kk + 2 * tig + 8];
        }
        uint32_t bf[4][2];
        #pragma unroll
        for (int nt = 0; nt < 4; nt++) {
            int cb = wn + nt * 8 + gid;
            bf[nt][0] = *(const uint32_t*)&Bs[cb * ST + kk + 2 * tig];
            bf[nt][1] = *(const uint32_t*)&Bs[cb * ST + kk + 2 * tig + 8];
        }
        #pragma unroll
        for (int mt = 0; mt < 2; mt++)
            #pragma unroll
            for (int nt = 0; nt < 4; nt++) {
                asm volatile(
                    "mma.sync.aligned.m16n8k16.row.col.f32.f16.f16.f32 "
                    "{%0,%1,%2,%3}, {%4,%5,%6,%7}, {%8,%9}, {%0,%1,%2,%3};\n"
                    : "+f"(acc[mt][nt][0]), "+f"(acc[mt][nt][1]),
                      "+f"(acc[mt][nt][2]), "+f"(acc[mt][nt][3])
                    : "r"(af[mt][0]), "r"(af[mt][1]),
                      "r"(af[mt][2]), "r"(af[mt][3]),
                      "r"(bf[nt][0]), "r"(bf[nt][1]));
            }
    }

    #pragma unroll
    for (int mt = 0; mt < 2; mt++) {
        int r0 = row0 + wm + mt * 16 + gid;
        int r1 = r0 + 8;
        #pragma unroll
        for (int nt = 0; nt < 4; nt++) {
            int col = wn + nt * 8 + 2 * tig;
            if (r0 < M) {
                float sc = rowscale[r0];
                *(__half2*)(C + (size_t)r0 * BN + col) =
                    __floats2half2_rn(acc[mt][nt][0] * sc, acc[mt][nt][1] * sc);
            }
            if (r1 < M) {
                float sc = rowscale[r1];
                *(__half2*)(C + (size_t)r1 * BN + col) =
                    __floats2half2_rn(acc[mt][nt][2] * sc, acc[mt][nt][3] * sc);
            }
        }
    }
}

// ---------------------------------------------------------------------------
// Layer-1 aggregation over UNSCALED h1. Masked full-width x8 loop.
__global__ void k_agg1(const float* __restrict__ b1, int n) {
    int node = blockIdx.x * (blockDim.x >> 5) + (threadIdx.x >> 5);
    if (node >= n) return;
    int lane = threadIdx.x & 31;

    const uint2* h = (const uint2*)g_h1;
    const float w = __ldg(&g_dinv[node]);

    uint2 sv = __ldg(&h[(size_t)node * 32 + lane]);
    float2 lo = __half22float2(*(__half2*)&sv.x);
    float2 hi = __half22float2(*(__half2*)&sv.y);
    float4 acc = make_float4(w * lo.x, w * lo.y, w * hi.x, w * hi.y);

    int j = g_off[node];
    const int jend = g_off[node + 1];
    while (j < jend) {
        int cnt = min(32, jend - j);
        int sidx = 0; float dv = 0.f;
        if (lane < cnt) { sidx = __ldg(&g_csr[j + lane]); dv = __ldg(&g_dinv[sidx]); }
        for (int t = 0; t < cnt; t += 8) {
            int s0 = __shfl_sync(0xffffffffu, sidx, t);
            int s1 = __shfl_sync(0xffffffffu, sidx, t + 1);
            int s2 = __shfl_sync(0xffffffffu, sidx, t + 2);
            int s3 = __shfl_sync(0xffffffffu, sidx, t + 3);
            int s4 = __shfl_sync(0xffffffffu, sidx, t + 4);
            int s5 = __shfl_sync(0xffffffffu, sidx, t + 5);
            int s6 = __shfl_sync(0xffffffffu, sidx, t + 6);
            int s7 = __shfl_sync(0xffffffffu, sidx, t + 7);
            float f0 = __shfl_sync(0xffffffffu, dv, t);
            float f1 = __shfl_sync(0xffffffffu, dv, t + 1);
            float f2 = __shfl_sync(0xffffffffu, dv, t + 2);
            float f3 = __shfl_sync(0xffffffffu, dv, t + 3);
            float f4 = __shfl_sync(0xffffffffu, dv, t + 4);
            float f5 = __shfl_sync(0xffffffffu, dv, t + 5);
            float f6 = __shfl_sync(0xffffffffu, dv, t + 6);
            float f7 = __shfl_sync(0xffffffffu, dv, t + 7);
            uint2 v0 = __ldg(&h[(size_t)s0 * 32 + lane]);
            uint2 v1 = __ldg(&h[(size_t)s1 * 32 + lane]);
            uint2 v2 = __ldg(&h[(size_t)s2 * 32 + lane]);
            uint2 v3 = __ldg(&h[(size_t)s3 * 32 + lane]);
            uint2 v4 = __ldg(&h[(size_t)s4 * 32 + lane]);
            uint2 v5 = __ldg(&h[(size_t)s5 * 32 + lane]);
            uint2 v6 = __ldg(&h[(size_t)s6 * 32 + lane]);
            uint2 v7 = __ldg(&h[(size_t)s7 * 32 + lane]);
            float2 p0 = __half22float2(*(__half2*)&v0.x), q0 = __half22float2(*(__half2*)&v0.y);
            float2 p1 = __half22float2(*(__half2*)&v1.x), q1 = __half22float2(*(__half2*)&v1.y);
            float2 p2 = __half22float2(*(__half2*)&v2.x), q2 = __half22float2(*(__half2*)&v2.y);
            float2 p3 = __half22float2(*(__half2*)&v3.x), q3 = __half22float2(*(__half2*)&v3.y);
            float2 p4 = __half22float2(*(__half2*)&v4.x), q4 = __half22float2(*(__half2*)&v4.y);
            float2 p5 = __half22float2(*(__half2*)&v5.x), q5 = __half22float2(*(__half2*)&v5.y);
            float2 p6 = __half22float2(*(__half2*)&v6.x), q6 = __half22float2(*(__half2*)&v6.y);
            float2 p7 = __half22float2(*(__half2*)&v7.x), q7 = __half22float2(*(__half2*)&v7.y);
            acc.x = fmaf(f0, p0.x, fmaf(f1, p1.x, fmaf(f2, p2.x, fmaf(f3, p3.x, acc.x))));
            acc.x = fmaf(f4, p4.x, fmaf(f5, p5.x, fmaf(f6, p6.x, fmaf(f7, p7.x, acc.x))));
            acc.y = fmaf(f0, p0.y, fmaf(f1, p1.y, fmaf(f2, p2.y, fmaf(f3, p3.y, acc.y))));
            acc.y = fmaf(f4, p4.y, fmaf(f5, p5.y, fmaf(f6, p6.y, fmaf(f7, p7.y, acc.y))));
            acc.z = fmaf(f0, q0.x, fmaf(f1, q1.x, fmaf(f2, q2.x, fmaf(f3, q3.x, acc.z))));
            acc.z = fmaf(f4, q4.x, fmaf(f5, q5.x, fmaf(f6, q6.x, fmaf(f7, q7.x, acc.z))));
            acc.w = fmaf(f0, q0.y, fmaf(f1, q1.y, fmaf(f2, q2.y, fmaf(f3, q3.y, acc.w))));
            acc.w = fmaf(f4, q4.y, fmaf(f5, q5.y, fmaf(f6, q6.y, fmaf(f7, q7.y, acc.w))));
        }
        j += cnt;
    }
    float4 b = ((const float4*)b1)[lane];
    uint2 o;
    *(__half2*)&o.x = __floats2half2_rn(fmaxf(acc.x * w + b.x, 0.f),
                                        fmaxf(acc.y * w + b.y, 0.f));
    *(__half2*)&o.y = __floats2half2_rn(fmaxf(acc.z * w + b.z, 0.f),
                                        fmaxf(acc.w * w + b.w, 0.f));
    ((uint2*)g_a1)[(size_t)node * 32 + lane] = o;
}

// Layer-2 aggregation over pre-scaled h2: 16-lane sub-warp per node
// (2 nodes/warp), uint2 per lane = 4 feats, masked x8 loop, fp32 out.
__global__ void k_agg2(const float* __restrict__ b2, float* __restrict__ out, int n) {
    int node = blockIdx.x * (blockDim.x >> 4) + (threadIdx.x >> 4);
    if (node >= n) return;
    int lane = threadIdx.x & 15;

    const uint2* h = (const uint2*)g_h2;    // 16 uint2 per 64-feat row
    uint2 sv = __ldg(&h[(size_t)node * 16 + lane]);
    float2 lo = __half22float2(*(__half2*)&sv.x);
    float2 hi = __half22float2(*(__half2*)&sv.y);
    float4 acc = make_float4(lo.x, lo.y, hi.x, hi.y);

    int j = g_off[node];
    const int jend = g_off[node + 1];
    while (j < jend) {
        int cnt = min(16, jend - j);
        int sidx = 0; float dv = 0.f;
        if (lane < cnt) { sidx = __ldg(&g_csr[j + lane]); dv = 1.0f; }
        for (int t = 0; t < cnt; t += 8) {
            int s0 = __shfl_sync(0xffffffffu, sidx, t,     16);
            int s1 = __shfl_sync(0xffffffffu, sidx, t + 1, 16);
            int s2 = __shfl_sync(0xffffffffu, sidx, t + 2, 16);
            int s3 = __shfl_sync(0xffffffffu, sidx, t + 3, 16);
            int s4 = __shfl_sync(0xffffffffu, sidx, t + 4, 16);
            int s5 = __shfl_sync(0xffffffffu, sidx, t + 5, 16);
            int s6 = __shfl_sync(0xffffffffu, sidx, t + 6, 16);
            int s7 = __shfl_sync(0xffffffffu, sidx, t + 7, 16);
            float f0 = __shfl_sync(0xffffffffu, dv, t,     16);
            float f1 = __shfl_sync(0xffffffffu, dv, t + 1, 16);
            float f2 = __shfl_sync(0xffffffffu, dv, t + 2, 16);
            float f3 = __shfl_sync(0xffffffffu, dv, t + 3, 16);
            float f4 = __shfl_sync(0xffffffffu, dv, t + 4, 16);
            float f5 = __shfl_sync(0xffffffffu, dv, t + 5, 16);
            float f6 = __shfl_sync(0xffffffffu, dv, t + 6, 16);
            float f7 = __shfl_sync(0xffffffffu, dv, t + 7, 16);
            uint2 v0 = __ldg(&h[(size_t)s0 * 16 + lane]);
            uint2 v1 = __ldg(&h[(size_t)s1 * 16 + lane]);
            uint2 v2 = __ldg(&h[(size_t)s2 * 16 + lane]);
            uint2 v3 = __ldg(&h[(size_t)s3 * 16 + lane]);
            uint2 v4 = __ldg(&h[(size_t)s4 * 16 + lane]);
            uint2 v5 = __ldg(&h[(size_t)s5 * 16 + lane]);
            uint2 v6 = __ldg(&h[(size_t)s6 * 16 + lane]);
            uint2 v7 = __ldg(&h[(size_t)s7 * 16 + lane]);
            float2 p0 = __half22float2(*(__half2*)&v0.x), q0 = __half22float2(*(__half2*)&v0.y);
            float2 p1 = __half22float2(*(__half2*)&v1.x), q1 = __half22float2(*(__half2*)&v1.y);
            float2 p2 = __half22float2(*(__half2*)&v2.x), q2 = __half22float2(*(__half2*)&v2.y);
            float2 p3 = __half22float2(*(__half2*)&v3.x), q3 = __half22float2(*(__half2*)&v3.y);
            float2 p4 = __half22float2(*(__half2*)&v4.x), q4 = __half22float2(*(__half2*)&v4.y);
            float2 p5 = __half22float2(*(__half2*)&v5.x), q5 = __half22float2(*(__half2*)&v5.y);
            float2 p6 = __half22float2(*(__half2*)&v6.x), q6 = __half22float2(*(__half2*)&v6.y);
            float2 p7 = __half22float2(*(__half2*)&v7.x), q7 = __half22float2(*(__half2*)&v7.y);
            acc.x = fmaf(f0, p0.x, fmaf(f1, p1.x, fmaf(f2, p2.x, fmaf(f3, p3.x, acc.x))));
            acc.x = fmaf(f4, p4.x, fmaf(f5, p5.x, fmaf(f6, p6.x, fmaf(f7, p7.x, acc.x))));
            acc.y = fmaf(f0, p0.y, fmaf(f1, p1.y, fmaf(f2, p2.y, fmaf(f3, p3.y, acc.y))));
            acc.y = fmaf(f4, p4.y, fmaf(f5, p5.y, fmaf(f6, p6.y, fmaf(f7, p7.y, acc.y))));
            acc.z = fmaf(f0, q0.x, fmaf(f1, q1.x, fmaf(f2, q2.x, fmaf(f3, q3.x, acc.z))));
            acc.z = fmaf(f4, q4.x, fmaf(f5, q5.x, fmaf(f6, q6.x, fmaf(f7, q7.x, acc.z))));
            acc.w = fmaf(f0, q0.y, fmaf(f1, q1.y, fmaf(f2, q2.y, fmaf(f3, q3.y, acc.w))));
            acc.w = fmaf(f4, q4.y, fmaf(f5, q5.y, fmaf(f6, q6.y, fmaf(f7, q7.y, acc.w))));
        }
        j += cnt;
    }
    float w = __ldg(&g_dinv[node]);
    float4 b = ((const float4*)b2)[lane];
    ((float4*)out)[(size_t)node * 16 + lane] =
        make_float4(acc.x * w + b.x, acc.y * w + b.y,
                    acc.z * w + b.z, acc.w * w + b.w);
}

// ---------------------------------------------------------------------------
extern "C" void kernel_launch(void* const* d_in, const int* in_sizes, int n_in,
                              void* d_out, int out_size) {
    const void*  eidx = d_in[0];
    const float* x    = (const float*)d_in[1];
    const float* W1   = (const float*)d_in[2];
    const float* b1   = (const float*)d_in[3];
    const float* W2   = (const float*)d_in[4];
    const float* b2   = (const float*)d_in[5];
    float* out = (float*)d_out;

    const int E = in_sizes[0] / 2;
    const int N = in_sizes[1] / NF1;

    __half *p_h1, *p_a1, *p_h2;
    float  *p_dinv;
    cudaGetSymbolAddress((void**)&p_h1,   g_h1);
    cudaGetSymbolAddress((void**)&p_a1,   g_a1);
    cudaGetSymbolAddress((void**)&p_h2,   g_h2);
    cudaGetSymbolAddress((void**)&p_dinv, g_dinv);

    static bool attr_done = false;
    if (!attr_done) {
        cudaFuncSetAttribute(gemm1_fp16, cudaFuncAttributeMaxDynamicSharedMemorySize, G1_SMEM);
        cudaFuncSetAttribute(gemm2_fp16, cudaFuncAttributeMaxDynamicSharedMemorySize, G2_SMEM);
        attr_done = true;
    }

    const int nb = (N + SCAN_ELEMS - 1) / SCAN_ELEMS;
    const int nscan = E < 2048 ? E : 2048;
    const int initN = (N > NF1 * NF1) ? N : NF1 * NF1;

    cudaStream_t s1;
    cudaStreamCreateWithFlags(&s1, cudaStreamNonBlocking);
    cudaEvent_t eFork, eG1;
    cudaEventCreateWithFlags(&eFork, cudaEventDisableTiming);
    cudaEventCreateWithFlags(&eG1,   cudaEventDisableTiming);

    k_init<<<(initN + 255) / 256, 256>>>((const long long*)eidx, nscan, N, W1, W2);
    cudaEventRecord(eFork, 0);
    cudaStreamWaitEvent(s1, eFork, 0);

    // branch B (s1): gemm1 (UNSCALED h1)
    gemm1_fp16<<<(N + G1_BM - 1) / G1_BM, 256, G1_SMEM, s1>>>(x, p_h1, N);
    cudaEventRecord(eG1, s1);

    // branch A (default): CSR build (3-phase scan, x4-wide edge pass)
    k_deg<<<((E + 3) / 4 + 255) / 256, 256>>>(eidx, E);
    k_scan1<<<nb, 256>>>(N);
    k_scan2<<<1, 128>>>(nb);
    k_scan3<<<nb, 256>>>(N, E);
    k_scatter<<<((E + 3) / 4 + 255) / 256, 256>>>(E);

    // join
    cudaStreamWaitEvent(0, eG1, 0);
    k_agg1<<<(N + 7) / 8, 256>>>(b1, N);
    gemm2_fp16<<<(N + G2_BM - 1) / G2_BM, 256, G2_SMEM>>>(p_a1, p_h2, p_dinv, N);
    k_agg2<<<(N + 15) / 16, 256>>>(b2, out, N);

    cudaEventDestroy(eFork);
    cudaEventDestroy(eG1);
    cudaStreamDestroy(s1);
}